// round 12
// baseline (speedup 1.0000x reference)
#include <cuda_runtime.h>
#include <cuda_bf16.h>
#include <cstdint>

#define B_     32
#define H_     2048
#define V_     128000
#define HIST_  2048
#define NT     128          // W rows per tile
#define NTILES (V_ / NT)    // 1000
#define GRID_G 296          // 148 SMs x 2 CTAs
#define KC     64           // K chunk
#define NCHUNK (H_ / KC)    // 32
#define CAP    1024

#define WSTRIDE_F 68
#define GEMM_SMEM (16384 + 2 * 34816)     // 86016

// ---------------- device scratch ----------------
__device__ __nv_bfloat16 g_ahi[B_ * H_];
__device__ __nv_bfloat16 g_alo[B_ * H_];
__device__ float         g_logits[(size_t)B_ * V_];
__device__ unsigned      g_tile_ctr;
__device__ unsigned      g_rowmax[B_];     // monotonic keys

// ---------------- helpers ----------------
__device__ __forceinline__ uint32_t smem_u32(const void* p) {
    uint32_t a;
    asm("{ .reg .u64 t; cvta.to.shared.u64 t, %1; cvt.u32.u64 %0, t; }" : "=r"(a) : "l"(p));
    return a;
}
#define SWZ(o) ((o) ^ (((o) >> 3) & 0x70))

#define CP16(dst, src) \
    asm volatile("cp.async.cg.shared.global [%0], [%1], 16;" :: "r"(dst), "l"(src))
#define CP_COMMIT() asm volatile("cp.async.commit_group;" ::: "memory")
#define CP_WAIT1()  asm volatile("cp.async.wait_group 1;" ::: "memory")

__device__ __forceinline__ uint32_t pack_bf16x2(float lo, float hi) {
    uint32_t r;
    asm("cvt.rn.bf16x2.f32 %0, %1, %2;" : "=r"(r) : "f"(hi), "f"(lo));
    return r;
}
__device__ __forceinline__ void ldmx4(uint32_t* r, uint32_t addr) {
    asm volatile("ldmatrix.sync.aligned.m8n8.x4.shared.b16 {%0,%1,%2,%3}, [%4];"
                 : "=r"(r[0]), "=r"(r[1]), "=r"(r[2]), "=r"(r[3]) : "r"(addr));
}
__device__ __forceinline__ void mma16816(float* d, const uint32_t* a,
                                         uint32_t b0, uint32_t b1) {
    asm volatile(
        "mma.sync.aligned.m16n8k16.row.col.f32.bf16.bf16.f32 "
        "{%0,%1,%2,%3}, {%4,%5,%6,%7}, {%8,%9}, {%0,%1,%2,%3};"
        : "+f"(d[0]), "+f"(d[1]), "+f"(d[2]), "+f"(d[3])
        : "r"(a[0]), "r"(a[1]), "r"(a[2]), "r"(a[3]), "r"(b0), "r"(b1));
}
__device__ __forceinline__ unsigned mono_key(float x) {
    const unsigned u = __float_as_uint(x);
    return (u & 0x80000000u) ? ~u : (u | 0x80000000u);
}
__device__ __forceinline__ float mono_dec(unsigned k) {
    return (k & 0x80000000u) ? __uint_as_float(k ^ 0x80000000u)
                             : __uint_as_float(~k);
}

// ---------------- reset (graph-replay determinism) ----------------
__global__ void reset_kernel() {
    if (threadIdx.x == 0) g_tile_ctr = 0u;
    if (threadIdx.x < B_) g_rowmax[threadIdx.x] = 0u;
}

// ---------------- K0: LayerNorm -> bf16 hi/lo (proven) ----------------
__global__ void __launch_bounds__(256) ln_kernel(const float* __restrict__ hs,
                                                 const float* __restrict__ gamma,
                                                 const float* __restrict__ beta) {
    __shared__ float sbuf[8];
    const int b = blockIdx.x, tid = threadIdx.x;
    const float* x = hs + (size_t)b * H_;

    float v[8];
#pragma unroll
    for (int i = 0; i < 8; i++) v[i] = x[i * 256 + tid];

    float s = 0.f;
#pragma unroll
    for (int i = 0; i < 8; i++) s += v[i];
#pragma unroll
    for (int off = 16; off >= 1; off >>= 1) s += __shfl_xor_sync(0xffffffffu, s, off);
    if ((tid & 31) == 0) sbuf[tid >> 5] = s;
    __syncthreads();
    if (tid == 0) {
        float t = 0.f;
        for (int i = 0; i < 8; i++) t += sbuf[i];
        sbuf[0] = t * (1.0f / H_);
    }
    __syncthreads();
    const float mean = sbuf[0];
    __syncthreads();

    float sq = 0.f;
#pragma unroll
    for (int i = 0; i < 8; i++) { float d = v[i] - mean; sq += d * d; }
#pragma unroll
    for (int off = 16; off >= 1; off >>= 1) sq += __shfl_xor_sync(0xffffffffu, sq, off);
    if ((tid & 31) == 0) sbuf[tid >> 5] = sq;
    __syncthreads();
    if (tid == 0) {
        float t = 0.f;
        for (int i = 0; i < 8; i++) t += sbuf[i];
        sbuf[0] = t * (1.0f / H_);
    }
    __syncthreads();
    const float rs = rsqrtf(sbuf[0] + 1e-5f);

#pragma unroll
    for (int i = 0; i < 8; i++) {
        const int k = i * 256 + tid;
        const float h = (v[i] - mean) * rs * gamma[k] + beta[k];
        const __nv_bfloat16 hi = __float2bfloat16(h);
        g_ahi[b * H_ + k] = hi;
        g_alo[b * H_ + k] = __float2bfloat16(h - __bfloat162float(hi));
    }
}

// ---------------- K1: persistent pipelined bf16 split GEMM ----------------
__global__ void __launch_bounds__(256, 2) gemm_mma(const float* __restrict__ W) {
    extern __shared__ __align__(16) char smem[];
    const uint32_t sb = smem_u32(smem);
    __shared__ int s_tile;
    __shared__ unsigned smax[B_];

    const int tid  = threadIdx.x;
    const int lane = tid & 31;
    const int wid  = tid >> 5;
    const int wn   = wid * 16;

    const int arow = lane & 15;
    const int koff = (lane & 16) ? 8 : 0;
    const int brow = wn + (lane >> 2);
    const int bk   = (lane & 3) * 2;

    for (;;) {
        if (tid == 0) s_tile = (int)atomicAdd(&g_tile_ctr, 1u);
        __syncthreads();
        const int tile = s_tile;
        if (tile >= NTILES) return;
        const int v0 = tile * NT;

        float d1[4][2][4];
        float d2[2][2][4];
#pragma unroll
        for (int mt = 0; mt < 4; mt++)
#pragma unroll
            for (int nt = 0; nt < 2; nt++)
#pragma unroll
                for (int i = 0; i < 4; i++) d1[mt][nt][i] = 0.f;
#pragma unroll
        for (int mt = 0; mt < 2; mt++)
#pragma unroll
            for (int nt = 0; nt < 2; nt++)
#pragma unroll
                for (int i = 0; i < 4; i++) d2[mt][nt][i] = 0.f;

        auto stage = [&](int c) {
            const int buf = c & 1;
            const int k0  = c * KC;
            const uint32_t ab = sb + buf * 8192;
            const uint32_t wb = sb + 16384 + buf * 34816;
#pragma unroll
            for (int i = tid; i < 512; i += 256) {
                const int r = i >> 3, q = i & 7;
                const void* src = (r < 32) ? (const void*)&g_ahi[r * H_ + k0 + q * 8]
                                           : (const void*)&g_alo[(r - 32) * H_ + k0 + q * 8];
                CP16(ab + SWZ(r * 128 + q * 16), src);
            }
#pragma unroll
            for (int i = tid; i < 2048; i += 256) {
                const int r = i >> 4, q = i & 15;
                CP16(wb + r * 272 + q * 16, W + (size_t)(v0 + r) * H_ + k0 + q * 4);
            }
        };

        stage(0);
        CP_COMMIT();

        for (int c = 0; c < NCHUNK; c++) {
            if (c + 1 < NCHUNK) stage(c + 1);
            CP_COMMIT();
            CP_WAIT1();
            __syncthreads();

            const int buf = c & 1;
            const uint32_t sA = sb + buf * 8192;
            const float* Wb = reinterpret_cast<const float*>(smem + 16384 + buf * 34816);

#pragma unroll
            for (int ks = 0; ks < 4; ks++) {
                const int kc = ks * 16 + koff;
                uint32_t a[4][4];
#pragma unroll
                for (int mt = 0; mt < 4; mt++)
                    ldmx4(a[mt], sA + SWZ((mt * 16 + arow) * 128 + kc * 2));

#pragma unroll
                for (int nt = 0; nt < 2; nt++) {
                    const float* wr = Wb + (brow + nt * 8) * WSTRIDE_F + ks * 16 + bk;
                    const float2 w0 = *reinterpret_cast<const float2*>(wr);
                    const float2 w1 = *reinterpret_cast<const float2*>(wr + 8);

                    const uint32_t bh0 = pack_bf16x2(w0.x, w0.y);
                    const uint32_t bh1 = pack_bf16x2(w1.x, w1.y);
                    const float r0 = w0.x - __uint_as_float(bh0 << 16);
                    const float r1 = w0.y - __uint_as_float(bh0 & 0xFFFF0000u);
                    const float r2 = w1.x - __uint_as_float(bh1 << 16);
                    const float r3 = w1.y - __uint_as_float(bh1 & 0xFFFF0000u);
                    const uint32_t bl0 = pack_bf16x2(r0, r1);
                    const uint32_t bl1 = pack_bf16x2(r2, r3);

#pragma unroll
                    for (int mt = 0; mt < 4; mt++)
                        mma16816(d1[mt][nt], a[mt], bh0, bh1);
#pragma unroll
                    for (int mt = 0; mt < 2; mt++)
                        mma16816(d2[mt][nt], a[mt], bl0, bl1);
                }
            }
            __syncthreads();
        }

        // epilogue: store logits + per-row max (monotonic keys)
        if (tid < B_) smax[tid] = 0u;
        __syncthreads();
#pragma unroll
        for (int mt = 0; mt < 2; mt++)
#pragma unroll
            for (int nt = 0; nt < 2; nt++)
#pragma unroll
                for (int hf = 0; hf < 2; hf++) {
                    const int b = mt * 16 + (lane >> 2) + hf * 8;
                    const int v = v0 + wn + nt * 8 + (lane & 3) * 2;
                    const float x0 = d1[mt][nt][hf * 2]     + d1[mt + 2][nt][hf * 2] +
                                     d2[mt][nt][hf * 2];
                    const float x1 = d1[mt][nt][hf * 2 + 1] + d1[mt + 2][nt][hf * 2 + 1] +
                                     d2[mt][nt][hf * 2 + 1];
                    *reinterpret_cast<float2*>(&g_logits[(size_t)b * V_ + v]) =
                        make_float2(x0, x1);
                    const unsigned k0 = mono_key(x0), k1 = mono_key(x1);
                    atomicMax(&smax[b], k0 > k1 ? k0 : k1);
                }
        __syncthreads();
        if (tid < B_ && smax[tid]) atomicMax(&g_rowmax[tid], smax[tid]);
    }
}

// ---------------- K2: fused penalty + windowed top-50 + top-p ----------------
__device__ __forceinline__ float apply_pen(float x, const unsigned* bm, int i) {
    if ((bm[i >> 5] >> (i & 31)) & 1u) x = (x < 0.f) ? x * 1.1f : x / 1.1f;
    return x;
}

__global__ void __launch_bounds__(1024, 1) select_kernel(const int* __restrict__ ids,
                                                         float* __restrict__ out,
                                                         int out_size) {
    __shared__ unsigned hist[1024];
    __shared__ unsigned bm[4000];
    __shared__ unsigned long long cand[CAP];
    __shared__ unsigned long long sel[50];
    __shared__ int s_cnt, s_tbin;

    const int b = blockIdx.x, tid = threadIdx.x;
    const float* row = g_logits + (size_t)b * V_;

    for (int i = tid; i < 4000; i += 1024) bm[i] = 0u;
    if (tid == 0) s_cnt = 0;
    __syncthreads();
    for (int i = tid; i < HIST_; i += 1024) {
        const int v = ids[b * HIST_ + i];
        if ((unsigned)v < (unsigned)V_) atomicOr(&bm[v >> 5], 1u << (v & 31));
    }
    __syncthreads();

    const float M = mono_dec(g_rowmax[b]);     // raw (pre-penalty) row max

    float w = 1.5f;
    int t;
    for (;;) {
        const float lo = M - w, scale = 1024.0f / w;
        hist[tid & 1023] = 0u;
        __syncthreads();
        for (int i4 = tid; i4 < V_ / 4; i4 += 1024) {
            const float4 xv = *reinterpret_cast<const float4*>(row + i4 * 4);
            const int i0 = i4 * 4;
            const float xs[4] = {apply_pen(xv.x, bm, i0),     apply_pen(xv.y, bm, i0 + 1),
                                 apply_pen(xv.z, bm, i0 + 2), apply_pen(xv.w, bm, i0 + 3)};
#pragma unroll
            for (int j = 0; j < 4; j++) {
                if (xs[j] >= lo) {
                    int bin = (int)((xs[j] - lo) * scale);
                    bin = bin > 1023 ? 1023 : bin;
                    atomicAdd(&hist[bin], 1u);
                }
            }
        }
        __syncthreads();
        if (tid == 0) {
            unsigned cum = 0;
            int tt = -1;
            for (int bin = 1023; bin >= 0; bin--) {
                cum += hist[bin];
                if (cum >= 50u) { tt = bin; break; }
            }
            s_tbin = tt;
        }
        __syncthreads();
        t = s_tbin;
        if (t >= 0) break;
        w *= 2.0f;
        __syncthreads();
    }

    {
        const float lo = M - w, scale = 1024.0f / w;
        for (int i4 = tid; i4 < V_ / 4; i4 += 1024) {
            const float4 xv = *reinterpret_cast<const float4*>(row + i4 * 4);
            const int i0 = i4 * 4;
            const float xs[4] = {apply_pen(xv.x, bm, i0),     apply_pen(xv.y, bm, i0 + 1),
                                 apply_pen(xv.z, bm, i0 + 2), apply_pen(xv.w, bm, i0 + 3)};
#pragma unroll
            for (int j = 0; j < 4; j++) {
                if (xs[j] >= lo) {
                    int bin = (int)((xs[j] - lo) * scale);
                    bin = bin > 1023 ? 1023 : bin;
                    if (bin >= t) {
                        const int pos = atomicAdd(&s_cnt, 1);
                        if (pos < CAP)
                            cand[pos] = ((unsigned long long)mono_key(xs[j]) << 32) |
                                        (unsigned)(0xffffffffu - (i0 + j));
                    }
                }
            }
        }
    }
    __syncthreads();
    const int cnt = (s_cnt < CAP) ? s_cnt : CAP;

    if (tid < 32) {
        for (int r = 0; r < 50; r++) {
            unsigned long long best = 0ull;
            int bidx = -1;
            for (int i = tid; i < cnt; i += 32)
                if (cand[i] > best) { best = cand[i]; bidx = i; }
#pragma unroll
            for (int off = 16; off >= 1; off >>= 1) {
                const unsigned long long ob = __shfl_xor_sync(0xffffffffu, best, off);
                const int oi = __shfl_xor_sync(0xffffffffu, bidx, off);
                if (ob > best) { best = ob; bidx = oi; }
            }
            if (tid == 0 && bidx >= 0) { sel[r] = best; cand[bidx] = 0ull; }
            __syncwarp();
        }
    }
    __syncthreads();

    if (tid == 0) {
        float vals[50];
        int   tok[50];
        for (int i = 0; i < 50; i++) {
            const unsigned long long k64 = sel[i];
            vals[i] = mono_dec((unsigned)(k64 >> 32));
            tok[i] = (int)(0xffffffffu - (unsigned)(k64 & 0xffffffffu));
        }
        const float m0 = vals[0];
        float e[50], ssum = 0.f;
        for (int i = 0; i < 50; i++) { e[i] = expf(vals[i] - m0); ssum += e[i]; }
        float cum = 0.f, filt[50];
        for (int i = 0; i < 50; i++) {
            cum += e[i] / ssum;
            const bool keep = (cum < 0.8f) || (i < 5);
            filt[i] = keep ? vals[i] : -1000.0f;
        }
        float m2 = filt[0];
        for (int i = 1; i < 50; i++) m2 = fmaxf(m2, filt[i]);
        float s2 = 0.f;
        for (int i = 0; i < 50; i++) s2 += expf(filt[i] - m2);
        const int toff = out_size >> 1;
        for (int i = 0; i < 50; i++) {
            out[b * 50 + i] = expf(filt[i] - m2) / s2;
            out[toff + b * 50 + i] = (float)tok[i];
        }
    }
}

// ---------------- launch ----------------
extern "C" void kernel_launch(void* const* d_in, const int* in_sizes, int n_in,
                              void* d_out, int out_size) {
    const int*   ids   = (const int*)d_in[0];
    const float* hs    = (const float*)d_in[1];
    const float* gamma = (const float*)d_in[2];
    const float* beta  = (const float*)d_in[3];
    const float* Wm    = (const float*)d_in[4];

    cudaFuncSetAttribute(gemm_mma, cudaFuncAttributeMaxDynamicSharedMemorySize, GEMM_SMEM);

    reset_kernel<<<1, 32>>>();
    ln_kernel<<<B_, 256>>>(hs, gamma, beta);
    gemm_mma<<<GRID_G, 256, GEMM_SMEM>>>(Wm);
    select_kernel<<<B_, 1024>>>(ids, (float*)d_out, out_size);
}

// round 14
// speedup vs baseline: 1.0100x; 1.0100x over previous
#include <cuda_runtime.h>
#include <cuda_bf16.h>
#include <cstdint>

#define B_     32
#define H_     2048
#define V_     128000
#define HIST_  2048
#define NT     128
#define NTILES (V_ / NT)    // 1000
#define GRID_G 296          // 148 SMs x 2 CTAs
#define KC     64
#define NCHUNK (H_ / KC)    // 32
#define CAP    1024
#define GCAP   16384
#define NSLICE 8
#define SLICE4 (V_ / 4 / NSLICE)   // 4000 float4 per slice
#define W0     1.25f

#define WSTRIDE_F 68
#define GEMM_SMEM (16384 + 2 * 34816)     // 86016

// ---------------- device scratch ----------------
__device__ __nv_bfloat16 g_ahi[B_ * H_];
__device__ __nv_bfloat16 g_alo[B_ * H_];
__device__ float         g_logits[(size_t)B_ * V_];
__device__ unsigned      g_tile_ctr;
__device__ unsigned      g_rowmax[B_];
__device__ int           g_cnt[B_];
__device__ unsigned      g_hist[B_][1024];
__device__ unsigned long long g_cand[B_][GCAP];

// ---------------- helpers ----------------
__device__ __forceinline__ uint32_t smem_u32(const void* p) {
    uint32_t a;
    asm("{ .reg .u64 t; cvta.to.shared.u64 t, %1; cvt.u32.u64 %0, t; }" : "=r"(a) : "l"(p));
    return a;
}
#define SWZ(o) ((o) ^ (((o) >> 3) & 0x70))

#define CP16(dst, src) \
    asm volatile("cp.async.cg.shared.global [%0], [%1], 16;" :: "r"(dst), "l"(src))
#define CP_COMMIT() asm volatile("cp.async.commit_group;" ::: "memory")
#define CP_WAIT1()  asm volatile("cp.async.wait_group 1;" ::: "memory")

__device__ __forceinline__ uint32_t pack_bf16x2(float lo, float hi) {
    uint32_t r;
    asm("cvt.rn.bf16x2.f32 %0, %1, %2;" : "=r"(r) : "f"(hi), "f"(lo));
    return r;
}
__device__ __forceinline__ void ldmx4(uint32_t* r, uint32_t addr) {
    asm volatile("ldmatrix.sync.aligned.m8n8.x4.shared.b16 {%0,%1,%2,%3}, [%4];"
                 : "=r"(r[0]), "=r"(r[1]), "=r"(r[2]), "=r"(r[3]) : "r"(addr));
}
__device__ __forceinline__ void mma16816(float* d, const uint32_t* a,
                                         uint32_t b0, uint32_t b1) {
    asm volatile(
        "mma.sync.aligned.m16n8k16.row.col.f32.bf16.bf16.f32 "
        "{%0,%1,%2,%3}, {%4,%5,%6,%7}, {%8,%9}, {%0,%1,%2,%3};"
        : "+f"(d[0]), "+f"(d[1]), "+f"(d[2]), "+f"(d[3])
        : "r"(a[0]), "r"(a[1]), "r"(a[2]), "r"(a[3]), "r"(b0), "r"(b1));
}
__device__ __forceinline__ unsigned mono_key(float x) {
    const unsigned u = __float_as_uint(x);
    return (u & 0x80000000u) ? ~u : (u | 0x80000000u);
}
__device__ __forceinline__ float mono_dec(unsigned k) {
    return (k & 0x80000000u) ? __uint_as_float(k ^ 0x80000000u)
                             : __uint_as_float(~k);
}
__device__ __forceinline__ float apply_pen(float x, const unsigned* bm, int i) {
    if ((bm[i >> 5] >> (i & 31)) & 1u) x = (x < 0.f) ? x * 1.1f : x / 1.1f;
    return x;
}

// ---------------- reset ----------------
__global__ void __launch_bounds__(1024) reset_kernel() {
    const int t = blockIdx.x * 1024 + threadIdx.x;
    if (t == 0) g_tile_ctr = 0u;
    if (t < B_) { g_rowmax[t] = 0u; g_cnt[t] = 0; }
    if (t < B_ * 1024) reinterpret_cast<unsigned*>(g_hist)[t] = 0u;
}

// ---------------- K0: LayerNorm -> bf16 hi/lo (proven) ----------------
__global__ void __launch_bounds__(256) ln_kernel(const float* __restrict__ hs,
                                                 const float* __restrict__ gamma,
                                                 const float* __restrict__ beta) {
    __shared__ float sbuf[8];
    const int b = blockIdx.x, tid = threadIdx.x;
    const float* x = hs + (size_t)b * H_;

    float v[8];
#pragma unroll
    for (int i = 0; i < 8; i++) v[i] = x[i * 256 + tid];

    float s = 0.f;
#pragma unroll
    for (int i = 0; i < 8; i++) s += v[i];
#pragma unroll
    for (int off = 16; off >= 1; off >>= 1) s += __shfl_xor_sync(0xffffffffu, s, off);
    if ((tid & 31) == 0) sbuf[tid >> 5] = s;
    __syncthreads();
    if (tid == 0) {
        float t = 0.f;
        for (int i = 0; i < 8; i++) t += sbuf[i];
        sbuf[0] = t * (1.0f / H_);
    }
    __syncthreads();
    const float mean = sbuf[0];
    __syncthreads();

    float sq = 0.f;
#pragma unroll
    for (int i = 0; i < 8; i++) { float d = v[i] - mean; sq += d * d; }
#pragma unroll
    for (int off = 16; off >= 1; off >>= 1) sq += __shfl_xor_sync(0xffffffffu, sq, off);
    if ((tid & 31) == 0) sbuf[tid >> 5] = sq;
    __syncthreads();
    if (tid == 0) {
        float t = 0.f;
        for (int i = 0; i < 8; i++) t += sbuf[i];
        sbuf[0] = t * (1.0f / H_);
    }
    __syncthreads();
    const float rs = rsqrtf(sbuf[0] + 1e-5f);

#pragma unroll
    for (int i = 0; i < 8; i++) {
        const int k = i * 256 + tid;
        const float h = (v[i] - mean) * rs * gamma[k] + beta[k];
        const __nv_bfloat16 hi = __float2bfloat16(h);
        g_ahi[b * H_ + k] = hi;
        g_alo[b * H_ + k] = __float2bfloat16(h - __bfloat162float(hi));
    }
}

// ---------------- K1: persistent pipelined bf16 split GEMM (R12-proven) ----------------
__global__ void __launch_bounds__(256, 2) gemm_mma(const float* __restrict__ W) {
    extern __shared__ __align__(16) char smem[];
    const uint32_t sb = smem_u32(smem);
    __shared__ int s_tile;
    __shared__ unsigned smax[B_];

    const int tid  = threadIdx.x;
    const int lane = tid & 31;
    const int wid  = tid >> 5;
    const int wn   = wid * 16;

    const int arow = lane & 15;
    const int koff = (lane & 16) ? 8 : 0;
    const int brow = wn + (lane >> 2);
    const int bk   = (lane & 3) * 2;

    for (;;) {
        if (tid == 0) s_tile = (int)atomicAdd(&g_tile_ctr, 1u);
        __syncthreads();
        const int tile = s_tile;
        if (tile >= NTILES) return;
        const int v0 = tile * NT;

        float d1[4][2][4];
        float d2[2][2][4];
#pragma unroll
        for (int mt = 0; mt < 4; mt++)
#pragma unroll
            for (int nt = 0; nt < 2; nt++)
#pragma unroll
                for (int i = 0; i < 4; i++) d1[mt][nt][i] = 0.f;
#pragma unroll
        for (int mt = 0; mt < 2; mt++)
#pragma unroll
            for (int nt = 0; nt < 2; nt++)
#pragma unroll
                for (int i = 0; i < 4; i++) d2[mt][nt][i] = 0.f;

        auto stage = [&](int c) {
            const int buf = c & 1;
            const int k0  = c * KC;
            const uint32_t ab = sb + buf * 8192;
            const uint32_t wb = sb + 16384 + buf * 34816;
#pragma unroll
            for (int i = tid; i < 512; i += 256) {
                const int r = i >> 3, q = i & 7;
                const void* src = (r < 32) ? (const void*)&g_ahi[r * H_ + k0 + q * 8]
                                           : (const void*)&g_alo[(r - 32) * H_ + k0 + q * 8];
                CP16(ab + SWZ(r * 128 + q * 16), src);
            }
#pragma unroll
            for (int i = tid; i < 2048; i += 256) {
                const int r = i >> 4, q = i & 15;
                CP16(wb + r * 272 + q * 16, W + (size_t)(v0 + r) * H_ + k0 + q * 4);
            }
        };

        stage(0);
        CP_COMMIT();

        for (int c = 0; c < NCHUNK; c++) {
            if (c + 1 < NCHUNK) stage(c + 1);
            CP_COMMIT();
            CP_WAIT1();
            __syncthreads();

            const int buf = c & 1;
            const uint32_t sA = sb + buf * 8192;
            const float* Wb = reinterpret_cast<const float*>(smem + 16384 + buf * 34816);

#pragma unroll
            for (int ks = 0; ks < 4; ks++) {
                const int kc = ks * 16 + koff;
                uint32_t a[4][4];
#pragma unroll
                for (int mt = 0; mt < 4; mt++)
                    ldmx4(a[mt], sA + SWZ((mt * 16 + arow) * 128 + kc * 2));

#pragma unroll
                for (int nt = 0; nt < 2; nt++) {
                    const float* wr = Wb + (brow + nt * 8) * WSTRIDE_F + ks * 16 + bk;
                    const float2 w0 = *reinterpret_cast<const float2*>(wr);
                    const float2 w1 = *reinterpret_cast<const float2*>(wr + 8);

                    const uint32_t bh0 = pack_bf16x2(w0.x, w0.y);
                    const uint32_t bh1 = pack_bf16x2(w1.x, w1.y);
                    const float r0 = w0.x - __uint_as_float(bh0 << 16);
                    const float r1 = w0.y - __uint_as_float(bh0 & 0xFFFF0000u);
                    const float r2 = w1.x - __uint_as_float(bh1 << 16);
                    const float r3 = w1.y - __uint_as_float(bh1 & 0xFFFF0000u);
                    const uint32_t bl0 = pack_bf16x2(r0, r1);
                    const uint32_t bl1 = pack_bf16x2(r2, r3);

#pragma unroll
                    for (int mt = 0; mt < 4; mt++)
                        mma16816(d1[mt][nt], a[mt], bh0, bh1);
#pragma unroll
                    for (int mt = 0; mt < 2; mt++)
                        mma16816(d2[mt][nt], a[mt], bl0, bl1);
                }
            }
            __syncthreads();
        }

        if (tid < B_) smax[tid] = 0u;
        __syncthreads();
#pragma unroll
        for (int mt = 0; mt < 2; mt++)
#pragma unroll
            for (int nt = 0; nt < 2; nt++)
#pragma unroll
                for (int hf = 0; hf < 2; hf++) {
                    const int b = mt * 16 + (lane >> 2) + hf * 8;
                    const int v = v0 + wn + nt * 8 + (lane & 3) * 2;
                    const float x0 = d1[mt][nt][hf * 2]     + d1[mt + 2][nt][hf * 2] +
                                     d2[mt][nt][hf * 2];
                    const float x1 = d1[mt][nt][hf * 2 + 1] + d1[mt + 2][nt][hf * 2 + 1] +
                                     d2[mt][nt][hf * 2 + 1];
                    *reinterpret_cast<float2*>(&g_logits[(size_t)b * V_ + v]) =
                        make_float2(x0, x1);
                    const unsigned k0 = mono_key(x0), k1 = mono_key(x1);
                    atomicMax(&smax[b], k0 > k1 ? k0 : k1);
                }
        __syncthreads();
        if (tid < B_ && smax[tid]) atomicMax(&g_rowmax[tid], smax[tid]);
    }
}

// ---------------- K2a: parallel candidate collection (32 rows x 8 slices) ----------------
__global__ void __launch_bounds__(1024, 1) collect_kernel(const int* __restrict__ ids) {
    __shared__ unsigned bm[4000];
    const int b   = blockIdx.x >> 3;
    const int sl  = blockIdx.x & (NSLICE - 1);
    const int tid = threadIdx.x;
    const float* row = g_logits + (size_t)b * V_;

    for (int i = tid; i < 4000; i += 1024) bm[i] = 0u;
    __syncthreads();
    for (int i = tid; i < HIST_; i += 1024) {
        const int v = ids[b * HIST_ + i];
        if ((unsigned)v < (unsigned)V_) atomicOr(&bm[v >> 5], 1u << (v & 31));
    }
    __syncthreads();

    const float M  = mono_dec(g_rowmax[b]);
    const float lo = M - W0;
    const float scale = 1024.0f / W0;
    const int base4 = sl * SLICE4;

    for (int i4r = tid; i4r < SLICE4; i4r += 1024) {      // exact slice bounds
        const int i4 = base4 + i4r;
        const float4 xv = *reinterpret_cast<const float4*>(row + i4 * 4);
        const int i0 = i4 * 4;
        const float xs[4] = {apply_pen(xv.x, bm, i0),     apply_pen(xv.y, bm, i0 + 1),
                             apply_pen(xv.z, bm, i0 + 2), apply_pen(xv.w, bm, i0 + 3)};
#pragma unroll
        for (int j = 0; j < 4; j++) {
            if (xs[j] >= lo) {
                int bin = (int)((xs[j] - lo) * scale);
                bin = bin > 1023 ? 1023 : bin;
                atomicAdd(&g_hist[b][bin], 1u);
                const int pos = atomicAdd(&g_cnt[b], 1);
                if (pos < GCAP)
                    g_cand[b][pos] = ((unsigned long long)mono_key(xs[j]) << 32) |
                                     (unsigned)(0xffffffffu - (i0 + j));
            }
        }
    }
}

// ---------------- K2b: finalize (threshold, filter, top-50, softmax) ----------------
__global__ void __launch_bounds__(1024, 1) final_kernel(const int* __restrict__ ids,
                                                        float* __restrict__ out,
                                                        int out_size) {
    __shared__ unsigned hist[1024];
    __shared__ unsigned bm[4000];
    __shared__ unsigned long long cand[CAP];
    __shared__ unsigned long long sel[50];
    __shared__ int s_cnt, s_tbin;

    const int b = blockIdx.x, tid = threadIdx.x;
    const float* row = g_logits + (size_t)b * V_;
    const float M = mono_dec(g_rowmax[b]);

    hist[tid & 1023] = g_hist[b][tid & 1023];
    if (tid == 0) s_cnt = 0;
    __syncthreads();
    if (tid == 0) {
        unsigned cum = 0;
        int tt = -1;
        for (int bin = 1023; bin >= 0; bin--) {
            cum += hist[bin];
            if (cum >= 50u) { tt = bin; break; }
        }
        s_tbin = tt;
    }
    __syncthreads();
    int t = s_tbin;
    const int gtotal = g_cnt[b];

    if (t >= 0 && gtotal <= GCAP) {
        const float lo = M - W0, scale = 1024.0f / W0;
        for (int i = tid; i < gtotal; i += 1024) {
            const unsigned long long k64 = g_cand[b][i];
            const float x = mono_dec((unsigned)(k64 >> 32));
            int bin = (int)((x - lo) * scale);
            bin = bin > 1023 ? 1023 : bin;
            if (bin >= t) {
                const int pos = atomicAdd(&s_cnt, 1);
                if (pos < CAP) cand[pos] = k64;
            }
        }
        __syncthreads();
    } else {
        // fallback: deterministic full scan with doubling window
        for (int i = tid; i < 4000; i += 1024) bm[i] = 0u;
        __syncthreads();
        for (int i = tid; i < HIST_; i += 1024) {
            const int v = ids[b * HIST_ + i];
            if ((unsigned)v < (unsigned)V_) atomicOr(&bm[v >> 5], 1u << (v & 31));
        }
        __syncthreads();

        float w = 2.0f * W0;
        for (;;) {
            const float lo = M - w, scale = 1024.0f / w;
            hist[tid & 1023] = 0u;
            __syncthreads();
            for (int i4 = tid; i4 < V_ / 4; i4 += 1024) {
                const float4 xv = *reinterpret_cast<const float4*>(row + i4 * 4);
                const int i0 = i4 * 4;
                const float xs[4] = {apply_pen(xv.x, bm, i0),     apply_pen(xv.y, bm, i0 + 1),
                                     apply_pen(xv.z, bm, i0 + 2), apply_pen(xv.w, bm, i0 + 3)};
#pragma unroll
                for (int j = 0; j < 4; j++) {
                    if (xs[j] >= lo) {
                        int bin = (int)((xs[j] - lo) * scale);
                        bin = bin > 1023 ? 1023 : bin;
                        atomicAdd(&hist[bin], 1u);
                    }
                }
            }
            __syncthreads();
            if (tid == 0) {
                unsigned cum = 0;
                int tt = -1;
                for (int bin = 1023; bin >= 0; bin--) {
                    cum += hist[bin];
                    if (cum >= 50u) { tt = bin; break; }
                }
                s_tbin = tt;
            }
            __syncthreads();
            t = s_tbin;
            if (t >= 0) {
                for (int i4 = tid; i4 < V_ / 4; i4 += 1024) {
                    const float4 xv = *reinterpret_cast<const float4*>(row + i4 * 4);
                    const int i0 = i4 * 4;
                    const float xs[4] = {apply_pen(xv.x, bm, i0),     apply_pen(xv.y, bm, i0 + 1),
                                         apply_pen(xv.z, bm, i0 + 2), apply_pen(xv.w, bm, i0 + 3)};
#pragma unroll
                    for (int j = 0; j < 4; j++) {
                        if (xs[j] >= lo) {
                            int bin = (int)((xs[j] - lo) * scale);
                            bin = bin > 1023 ? 1023 : bin;
                            if (bin >= t) {
                                const int pos = atomicAdd(&s_cnt, 1);
                                if (pos < CAP)
                                    cand[pos] = ((unsigned long long)mono_key(xs[j]) << 32) |
                                                (unsigned)(0xffffffffu - (i0 + j));
                            }
                        }
                    }
                }
                __syncthreads();
                break;
            }
            w *= 2.0f;
            __syncthreads();
        }
    }

    const int cnt = (s_cnt < CAP) ? s_cnt : CAP;

    if (tid < 32) {
        for (int r = 0; r < 50; r++) {
            unsigned long long best = 0ull;
            int bidx = -1;
            for (int i = tid; i < cnt; i += 32)
                if (cand[i] > best) { best = cand[i]; bidx = i; }
#pragma unroll
            for (int off = 16; off >= 1; off >>= 1) {
                const unsigned long long ob = __shfl_xor_sync(0xffffffffu, best, off);
                const int oi = __shfl_xor_sync(0xffffffffu, bidx, off);
                if (ob > best) { best = ob; bidx = oi; }
            }
            if (tid == 0 && bidx >= 0) { sel[r] = best; cand[bidx] = 0ull; }
            __syncwarp();
        }
    }
    __syncthreads();

    if (tid == 0) {
        float vals[50];
        int   tok[50];
        for (int i = 0; i < 50; i++) {
            const unsigned long long k64 = sel[i];
            vals[i] = mono_dec((unsigned)(k64 >> 32));
            tok[i] = (int)(0xffffffffu - (unsigned)(k64 & 0xffffffffu));
        }
        const float m0 = vals[0];
        float e[50], ssum = 0.f;
        for (int i = 0; i < 50; i++) { e[i] = expf(vals[i] - m0); ssum += e[i]; }
        float cum = 0.f, filt[50];
        for (int i = 0; i < 50; i++) {
            cum += e[i] / ssum;
            const bool keep = (cum < 0.8f) || (i < 5);
            filt[i] = keep ? vals[i] : -1000.0f;
        }
        float m2 = filt[0];
        for (int i = 1; i < 50; i++) m2 = fmaxf(m2, filt[i]);
        float s2 = 0.f;
        for (int i = 0; i < 50; i++) s2 += expf(filt[i] - m2);
        const int toff = out_size >> 1;
        for (int i = 0; i < 50; i++) {
            out[b * 50 + i] = expf(filt[i] - m2) / s2;
            out[toff + b * 50 + i] = (float)tok[i];
        }
    }
}

// ---------------- launch ----------------
extern "C" void kernel_launch(void* const* d_in, const int* in_sizes, int n_in,
                              void* d_out, int out_size) {
    const int*   ids   = (const int*)d_in[0];
    const float* hs    = (const float*)d_in[1];
    const float* gamma = (const float*)d_in[2];
    const float* beta  = (const float*)d_in[3];
    const float* Wm    = (const float*)d_in[4];

    cudaFuncSetAttribute(gemm_mma, cudaFuncAttributeMaxDynamicSharedMemorySize, GEMM_SMEM);

    reset_kernel<<<B_, 1024>>>();
    ln_kernel<<<B_, 256>>>(hs, gamma, beta);
    gemm_mma<<<GRID_G, 256, GEMM_SMEM>>>(Wm);
    collect_kernel<<<B_ * NSLICE, 1024>>>(ids);
    final_kernel<<<B_, 1024>>>(ids, (float*)d_out, out_size);
}